// round 3
// baseline (speedup 1.0000x reference)
#include <cuda_runtime.h>
#include <math.h>

#define TT 512
#define NN 128
#define II 256
#define HH 512
#define CC 128
#define NH (NN*HH)        // 65536
#define RNN_BLOCKS 128
#define LOGITS_OFF 0
#define H_OFF (NN*CC)     // 16384

// ---------------- scratch (device globals; no allocations allowed) -------------
__device__ float g_xp[TT*NN*HH];      // x-projection for current layer (128 MB)
__device__ float g_out0[TT*NN*HH];    // layer-0 outputs (128 MB)
__device__ float g_h[NH];             // current hidden state (in-place updated)
__device__ float g_part[8*NH];        // K-split partial sums (2 MB)
__device__ int   g_cnt[TT];           // active-row count per timestep
__device__ unsigned g_bar_count;
__device__ volatile unsigned g_bar_gen;

// ---------------- grid barrier (sense/generation, persistent kernel) -----------
__device__ __forceinline__ void grid_barrier(unsigned* gen_sh, int nblk) {
    __syncthreads();
    if (threadIdx.x == 0) {
        unsigned g = *gen_sh;
        __threadfence();
        unsigned prev = atomicAdd(&g_bar_count, 1u);
        if (prev == (unsigned)(nblk - 1)) {
            g_bar_count = 0u;
            __threadfence();
            g_bar_gen = g + 1u;
        } else {
            while (g_bar_gen == g) { }
        }
        *gen_sh = g + 1u;
    }
    __syncthreads();
}

// ---------------- cnt[t] = #(lengths > t); lengths sorted descending -----------
__global__ void count_kernel(const int* __restrict__ len) {
    int t = threadIdx.x;
    int c = 0;
    #pragma unroll 8
    for (int n = 0; n < NN; n++) c += (len[n] > t) ? 1 : 0;
    g_cnt[t] = c;
}

__global__ void init_h_kernel(const float* __restrict__ h0, int layer) {
    int i = blockIdx.x * blockDim.x + threadIdx.x;
    if (i < NH) g_h[i] = h0[layer * NH + i];
}

__global__ void copy_h_kernel(float* __restrict__ dout, int layer) {
    int i = blockIdx.x * blockDim.x + threadIdx.x;
    if (i < NH) dout[H_OFF + layer * NH + i] = g_h[i];
}

// ---------------- generic GEMM + bias:  C[m, j] = A[m, :K] . W[j, :K] + b1 + b2 -
// grid: (Hout/64, Mrows/64, Tdim); block row range skipped if inactive (packed).
// asel: 0 -> Aptr, 1 -> g_out0, 2 -> g_h.  csel: 0 -> g_xp, 1 -> Cptr.
__global__ __launch_bounds__(256)
void gemm_bias_kernel(const float* __restrict__ Aptr, int asel,
                      const float* __restrict__ W,
                      const float* __restrict__ b1, const float* __restrict__ b2,
                      float* __restrict__ Cptr, int csel,
                      int K, int Hout, int useCnt)
{
    const float* A = (asel == 0) ? Aptr : ((asel == 1) ? g_out0 : g_h);
    float* C = (csel == 0) ? g_xp : Cptr;

    int t = blockIdx.z;
    if (useCnt && (int)(blockIdx.y * 64) >= g_cnt[t]) return;
    int rowbase = t * NN + blockIdx.y * 64;
    int jbase   = blockIdx.x * 64;

    __shared__ float As[16][68];
    __shared__ float Bs[16][68];

    int tid  = threadIdx.x;
    int lrow = tid >> 2;          // 0..63
    int lk4  = (tid & 3) * 4;     // 0,4,8,12
    int tm   = tid & 15;          // m-group
    int tn   = tid >> 4;          // j-group

    float acc[4][4] = {};

    const float* Arow = A + (size_t)(rowbase + lrow) * K + lk4;
    const float* Wrow = W + (size_t)(jbase  + lrow) * K + lk4;

    for (int k0 = 0; k0 < K; k0 += 16) {
        float4 av = *(const float4*)(Arow + k0);
        float4 bv = *(const float4*)(Wrow + k0);
        __syncthreads();
        As[lk4+0][lrow] = av.x; As[lk4+1][lrow] = av.y;
        As[lk4+2][lrow] = av.z; As[lk4+3][lrow] = av.w;
        Bs[lk4+0][lrow] = bv.x; Bs[lk4+1][lrow] = bv.y;
        Bs[lk4+2][lrow] = bv.z; Bs[lk4+3][lrow] = bv.w;
        __syncthreads();
        #pragma unroll
        for (int kk = 0; kk < 16; kk++) {
            float4 a4 = *(const float4*)&As[kk][tm * 4];
            float4 b4 = *(const float4*)&Bs[kk][tn * 4];
            acc[0][0] = fmaf(a4.x, b4.x, acc[0][0]);
            acc[0][1] = fmaf(a4.x, b4.y, acc[0][1]);
            acc[0][2] = fmaf(a4.x, b4.z, acc[0][2]);
            acc[0][3] = fmaf(a4.x, b4.w, acc[0][3]);
            acc[1][0] = fmaf(a4.y, b4.x, acc[1][0]);
            acc[1][1] = fmaf(a4.y, b4.y, acc[1][1]);
            acc[1][2] = fmaf(a4.y, b4.z, acc[1][2]);
            acc[1][3] = fmaf(a4.y, b4.w, acc[1][3]);
            acc[2][0] = fmaf(a4.z, b4.x, acc[2][0]);
            acc[2][1] = fmaf(a4.z, b4.y, acc[2][1]);
            acc[2][2] = fmaf(a4.z, b4.z, acc[2][2]);
            acc[2][3] = fmaf(a4.z, b4.w, acc[2][3]);
            acc[3][0] = fmaf(a4.w, b4.x, acc[3][0]);
            acc[3][1] = fmaf(a4.w, b4.y, acc[3][1]);
            acc[3][2] = fmaf(a4.w, b4.z, acc[3][2]);
            acc[3][3] = fmaf(a4.w, b4.w, acc[3][3]);
        }
    }

    int jc = jbase + tn * 4;
    float bb0 = b1[jc+0], bb1 = b1[jc+1], bb2 = b1[jc+2], bb3 = b1[jc+3];
    if (b2) { bb0 += b2[jc+0]; bb1 += b2[jc+1]; bb2 += b2[jc+2]; bb3 += b2[jc+3]; }
    #pragma unroll
    for (int i = 0; i < 4; i++) {
        int row = rowbase + tm * 4 + i;
        float4 v = make_float4(acc[i][0] + bb0, acc[i][1] + bb1,
                               acc[i][2] + bb2, acc[i][3] + bb3);
        *(float4*)(C + (size_t)row * Hout + jc) = v;
    }
}

// ---------------- persistent recurrence kernel ---------------------------------
// 128 CTAs = 16 j-tiles (32 cols) x 8 k-chunks (64). Whh slice lives in smem for
// the whole sequence. Per step: phase1 GEMM partials (only active n-rows),
// barrier, phase2 reduce + tanh + in-place h update (+ optional out store),
// barrier.
__global__ __launch_bounds__(256)
void rnn_kernel(const float* __restrict__ Whh, int storeOut)
{
    __shared__ float Ws[64][32];    // W^T slice: [k][j]
    __shared__ float hs[64][128];   // h^T slice: [k][n]
    __shared__ unsigned gen_sh;

    int tid = threadIdx.x;
    int cta = blockIdx.x;
    int jt = cta & 15, kc = cta >> 4;
    int j0 = jt * 32, k0 = kc * 64;

    {   // one-time Whh slice load (transposed)
        int jrow = tid >> 3;          // 0..31
        int kq   = (tid & 7) * 8;     // 0..56
        #pragma unroll
        for (int q = 0; q < 8; q++)
            Ws[kq + q][jrow] = Whh[(size_t)(j0 + jrow) * HH + k0 + kq + q];
    }
    if (tid == 0) gen_sh = g_bar_gen;
    __syncthreads();

    int n = tid & 127, half = tid >> 7;
    int tn = tid & 31, tj = tid >> 5;
    int nb = tn * 4, jb = tj * 4;

    for (int t = 0; t < TT; t++) {
        int cnt = g_cnt[t];
        if (cnt == 0) break;   // uniform across grid (cnt monotone non-increasing)

        // stage h^T for our k-chunk (cross-CTA data -> bypass L1)
        #pragma unroll
        for (int q = 0; q < 8; q++) {
            int kl = half * 32 + q * 4;
            float4 v = __ldcg((const float4*)&g_h[n * HH + k0 + kl]);
            hs[kl+0][n] = v.x; hs[kl+1][n] = v.y;
            hs[kl+2][n] = v.z; hs[kl+3][n] = v.w;
        }
        __syncthreads();

        if (nb < cnt) {
            float acc[4][4] = {};
            #pragma unroll 8
            for (int k = 0; k < 64; k++) {
                float4 a4 = *(const float4*)&hs[k][nb];
                float4 b4 = *(const float4*)&Ws[k][jb];
                acc[0][0] = fmaf(a4.x, b4.x, acc[0][0]);
                acc[0][1] = fmaf(a4.x, b4.y, acc[0][1]);
                acc[0][2] = fmaf(a4.x, b4.z, acc[0][2]);
                acc[0][3] = fmaf(a4.x, b4.w, acc[0][3]);
                acc[1][0] = fmaf(a4.y, b4.x, acc[1][0]);
                acc[1][1] = fmaf(a4.y, b4.y, acc[1][1]);
                acc[1][2] = fmaf(a4.y, b4.z, acc[1][2]);
                acc[1][3] = fmaf(a4.y, b4.w, acc[1][3]);
                acc[2][0] = fmaf(a4.z, b4.x, acc[2][0]);
                acc[2][1] = fmaf(a4.z, b4.y, acc[2][1]);
                acc[2][2] = fmaf(a4.z, b4.z, acc[2][2]);
                acc[2][3] = fmaf(a4.z, b4.w, acc[2][3]);
                acc[3][0] = fmaf(a4.w, b4.x, acc[3][0]);
                acc[3][1] = fmaf(a4.w, b4.y, acc[3][1]);
                acc[3][2] = fmaf(a4.w, b4.z, acc[3][2]);
                acc[3][3] = fmaf(a4.w, b4.w, acc[3][3]);
            }
            #pragma unroll
            for (int i = 0; i < 4; i++) {
                *(float4*)&g_part[(size_t)kc * NH + (nb + i) * HH + j0 + jb] =
                    make_float4(acc[i][0], acc[i][1], acc[i][2], acc[i][3]);
            }
        }

        grid_barrier(&gen_sh, RNN_BLOCKS);

        // phase 2: reduce partials + xproj, tanh, in-place h update
        {
            const float* xpt = g_xp + (size_t)t * NH;
            float* outt = g_out0 + (size_t)t * NH;
            int total = cnt * HH;
            for (int idx = cta * 256 + tid; idx < total; idx += RNN_BLOCKS * 256) {
                float s = xpt[idx];
                #pragma unroll
                for (int p = 0; p < 8; p++)
                    s += __ldcg(&g_part[p * NH + idx]);
                float v = tanhf(s);
                g_h[idx] = v;
                if (storeOut) outt[idx] = v;
            }
        }

        grid_barrier(&gen_sh, RNN_BLOCKS);
    }
}

// ---------------- host launcher -------------------------------------------------
extern "C" void kernel_launch(void* const* d_in, const int* in_sizes, int n_in,
                              void* d_out, int out_size) {
    const float* x    = (const float*)d_in[0];
    const float* h0   = (const float*)d_in[1];
    const int*   len  = (const int*)  d_in[2];
    const float* Wih0 = (const float*)d_in[3];
    const float* bih0 = (const float*)d_in[4];
    const float* Whh0 = (const float*)d_in[5];
    const float* bhh0 = (const float*)d_in[6];
    const float* Wih1 = (const float*)d_in[7];
    const float* bih1 = (const float*)d_in[8];
    const float* Whh1 = (const float*)d_in[9];
    const float* bhh1 = (const float*)d_in[10];
    const float* Wfc  = (const float*)d_in[11];
    const float* bfc  = (const float*)d_in[12];
    float* out = (float*)d_out;

    count_kernel<<<1, TT>>>(len);

    // ---- layer 0 ----
    init_h_kernel<<<NH/256, 256>>>(h0, 0);
    gemm_bias_kernel<<<dim3(HH/64, NN/64, TT), 256>>>(
        x, /*asel=*/0, Wih0, bih0, bhh0, nullptr, /*csel=*/0, II, HH, /*useCnt=*/1);
    rnn_kernel<<<RNN_BLOCKS, 256>>>(Whh0, /*storeOut=*/1);
    copy_h_kernel<<<NH/256, 256>>>(out, 0);

    // ---- layer 1 ----
    init_h_kernel<<<NH/256, 256>>>(h0, 1);
    gemm_bias_kernel<<<dim3(HH/64, NN/64, TT), 256>>>(
        nullptr, /*asel=*/1, Wih1, bih1, bhh1, nullptr, /*csel=*/0, HH, HH, /*useCnt=*/1);
    rnn_kernel<<<RNN_BLOCKS, 256>>>(Whh1, /*storeOut=*/0);
    copy_h_kernel<<<NH/256, 256>>>(out, 1);

    // ---- logits = h1 @ Wfc^T + bfc  (last valid output == final frozen h1) ----
    gemm_bias_kernel<<<dim3(CC/64, NN/64, 1), 256>>>(
        nullptr, /*asel=*/2, Wfc, bfc, nullptr, out + LOGITS_OFF, /*csel=*/1,
        HH, CC, /*useCnt=*/0);
}

// round 4
// speedup vs baseline: 1.1217x; 1.1217x over previous
#include <cuda_runtime.h>
#include <math.h>

#define TT 512
#define NN 128
#define II 256
#define HH 512
#define CC 128
#define NH (NN*HH)
#define RNN_BLOCKS 128
#define H_OFF (NN*CC)

__device__ float g_xp[TT*NN*HH];
__device__ float g_out0[TT*NN*HH];
__device__ float g_h[NH];
__device__ float g_part[8*NH];
__device__ int   g_cnt[TT];
__device__ unsigned g_bar_count;
__device__ volatile unsigned g_bar_gen;

__device__ __forceinline__ void grid_barrier(unsigned* gen_sh, int nblk) {
    __syncthreads();
    if (threadIdx.x == 0) {
        unsigned g = *gen_sh;
        __threadfence();
        unsigned prev = atomicAdd(&g_bar_count, 1u);
        if (prev == (unsigned)(nblk - 1)) {
            g_bar_count = 0u;
            __threadfence();
            g_bar_gen = g + 1u;
        } else {
            while (g_bar_gen == g) { }
        }
        *gen_sh = g + 1u;
    }
    __syncthreads();
}

__global__ void count_kernel(const int* __restrict__ len) {
    int t = threadIdx.x, c = 0;
    #pragma unroll 8
    for (int n = 0; n < NN; n++) c += (len[n] > t) ? 1 : 0;
    g_cnt[t] = c;
}

__global__ void init_h_kernel(const float* __restrict__ h0, int layer) {
    int i = blockIdx.x * blockDim.x + threadIdx.x;
    if (i < NH) g_h[i] = h0[layer * NH + i];
}

__global__ void copy_h_kernel(float* __restrict__ dout, int layer) {
    int i = blockIdx.x * blockDim.x + threadIdx.x;
    if (i < NH) dout[H_OFF + layer * NH + i] = g_h[i];
}

// ---- GEMM + bias: C[m,j] = A[m,:K].W[j,:K] + b1 (+b2). 64x128 tile, 128 thr,
// 8x8 microtile, double-buffered smem. asel: 0=Aptr 1=g_out0 2=g_h; csel: 0=g_xp 1=Cptr.
__global__ __launch_bounds__(128)
void gemm64(const float* __restrict__ Aptr, int asel,
            const float* __restrict__ W,
            const float* __restrict__ b1, const float* __restrict__ b2,
            float* __restrict__ Cptr, int csel, int K, int Hout, int useCnt)
{
    const float* A = (asel == 0) ? Aptr : ((asel == 1) ? g_out0 : g_h);
    float* C = (csel == 0) ? g_xp : Cptr;

    int row0;
    if (useCnt) {
        int t = blockIdx.y >> 1, nt = blockIdx.y & 1;
        if (nt * 64 >= g_cnt[t]) return;
        row0 = t * NN + nt * 64;
    } else {
        row0 = blockIdx.y * 64;
    }
    int j0 = blockIdx.x * 128;
    int tid = threadIdx.x;

    __shared__ float As[2][8][68];
    __shared__ float Bs[2][8][132];

    int ar = tid >> 1;
    int ak = (tid & 1) * 4;
    const float* Ap = A + (size_t)(row0 + ar) * K + ak;
    const float* Wp = W + (size_t)(j0 + tid) * K;
    int KT = K >> 3;

    float4 a_r  = *(const float4*)(Ap);
    float4 b_r0 = *(const float4*)(Wp);
    float4 b_r1 = *(const float4*)(Wp + 4);
    As[0][ak+0][ar] = a_r.x; As[0][ak+1][ar] = a_r.y;
    As[0][ak+2][ar] = a_r.z; As[0][ak+3][ar] = a_r.w;
    Bs[0][0][tid] = b_r0.x; Bs[0][1][tid] = b_r0.y;
    Bs[0][2][tid] = b_r0.z; Bs[0][3][tid] = b_r0.w;
    Bs[0][4][tid] = b_r1.x; Bs[0][5][tid] = b_r1.y;
    Bs[0][6][tid] = b_r1.z; Bs[0][7][tid] = b_r1.w;
    __syncthreads();

    int tm = tid & 7;    // 8 row-groups of 8
    int tj = tid >> 3;   // 16 col-groups of 8
    float acc[8][8] = {};

    for (int kt = 0; kt < KT; kt++) {
        int cur = kt & 1;
        bool nxt = (kt + 1 < KT);
        if (nxt) {
            int k0 = (kt + 1) << 3;
            a_r  = *(const float4*)(Ap + k0);
            b_r0 = *(const float4*)(Wp + k0);
            b_r1 = *(const float4*)(Wp + k0 + 4);
        }
        #pragma unroll
        for (int kk = 0; kk < 8; kk++) {
            float4 a0 = *(const float4*)&As[cur][kk][tm*8];
            float4 a1 = *(const float4*)&As[cur][kk][tm*8+4];
            float4 b0 = *(const float4*)&Bs[cur][kk][tj*8];
            float4 b1v= *(const float4*)&Bs[cur][kk][tj*8+4];
            float av[8] = {a0.x,a0.y,a0.z,a0.w,a1.x,a1.y,a1.z,a1.w};
            float bv[8] = {b0.x,b0.y,b0.z,b0.w,b1v.x,b1v.y,b1v.z,b1v.w};
            #pragma unroll
            for (int i = 0; i < 8; i++)
                #pragma unroll
                for (int j = 0; j < 8; j++)
                    acc[i][j] = fmaf(av[i], bv[j], acc[i][j]);
        }
        if (nxt) {
            int nb = cur ^ 1;
            As[nb][ak+0][ar] = a_r.x; As[nb][ak+1][ar] = a_r.y;
            As[nb][ak+2][ar] = a_r.z; As[nb][ak+3][ar] = a_r.w;
            Bs[nb][0][tid] = b_r0.x; Bs[nb][1][tid] = b_r0.y;
            Bs[nb][2][tid] = b_r0.z; Bs[nb][3][tid] = b_r0.w;
            Bs[nb][4][tid] = b_r1.x; Bs[nb][5][tid] = b_r1.y;
            Bs[nb][6][tid] = b_r1.z; Bs[nb][7][tid] = b_r1.w;
        }
        __syncthreads();
    }

    int jc = j0 + tj * 8;
    float bb[8];
    #pragma unroll
    for (int j = 0; j < 8; j++)
        bb[j] = b1[jc+j] + (b2 ? b2[jc+j] : 0.0f);
    #pragma unroll
    for (int i = 0; i < 8; i++) {
        int row = row0 + tm * 8 + i;
        float4 v0 = make_float4(acc[i][0]+bb[0], acc[i][1]+bb[1],
                                acc[i][2]+bb[2], acc[i][3]+bb[3]);
        float4 v1 = make_float4(acc[i][4]+bb[4], acc[i][5]+bb[5],
                                acc[i][6]+bb[6], acc[i][7]+bb[7]);
        *(float4*)(C + (size_t)row * Hout + jc)     = v0;
        *(float4*)(C + (size_t)row * Hout + jc + 4) = v1;
    }
}

// ---- persistent recurrence: 128 CTAs = 16 j-tiles(32) x 8 k-chunks(64) --------
__global__ __launch_bounds__(256)
void rnn_kernel(const float* __restrict__ Whh, int storeOut)
{
    __shared__ float Ws[64][32];
    __shared__ float hs[64][128];
    __shared__ unsigned gen_sh;

    int tid = threadIdx.x, cta = blockIdx.x;
    int jt = cta & 15, kc = cta >> 4;
    int j0 = jt * 32, k0 = kc * 64;

    {
        int jrow = tid >> 3, kq = (tid & 7) * 8;
        #pragma unroll
        for (int q = 0; q < 8; q++)
            Ws[kq + q][jrow] = Whh[(size_t)(j0 + jrow) * HH + k0 + kq + q];
    }
    if (tid == 0) gen_sh = g_bar_gen;
    __syncthreads();

    int n = tid & 127, half = tid >> 7;
    int tn = tid & 31, tj = tid >> 5;
    int nb = tn * 4, jb = tj * 4;

    for (int t = 0; t < TT; t++) {
        int cnt = g_cnt[t];
        if (cnt == 0) break;

        if (n < cnt) {
            #pragma unroll
            for (int q = 0; q < 8; q++) {
                int kl = half * 32 + q * 4;
                float4 v = __ldcg((const float4*)&g_h[n * HH + k0 + kl]);
                hs[kl+0][n] = v.x; hs[kl+1][n] = v.y;
                hs[kl+2][n] = v.z; hs[kl+3][n] = v.w;
            }
        }
        __syncthreads();

        if (nb < cnt) {
            float acc[4][4] = {};
            #pragma unroll 8
            for (int k = 0; k < 64; k++) {
                float4 a4 = *(const float4*)&hs[k][nb];
                float4 b4 = *(const float4*)&Ws[k][jb];
                float av[4] = {a4.x,a4.y,a4.z,a4.w};
                float bv[4] = {b4.x,b4.y,b4.z,b4.w};
                #pragma unroll
                for (int i = 0; i < 4; i++)
                    #pragma unroll
                    for (int j = 0; j < 4; j++)
                        acc[i][j] = fmaf(av[i], bv[j], acc[i][j]);
            }
            #pragma unroll
            for (int i = 0; i < 4; i++)
                *(float4*)&g_part[(size_t)kc * NH + (nb + i) * HH + j0 + jb] =
                    make_float4(acc[i][0], acc[i][1], acc[i][2], acc[i][3]);
        }

        grid_barrier(&gen_sh, RNN_BLOCKS);

        {
            const float* xpt = g_xp + (size_t)t * NH;
            float* outt = g_out0 + (size_t)t * NH;
            int total = cnt * HH;
            for (int idx = cta * 256 + tid; idx < total; idx += RNN_BLOCKS * 256) {
                float s = xpt[idx];
                #pragma unroll
                for (int p = 0; p < 8; p++)
                    s += __ldcg(&g_part[p * NH + idx]);
                float v = tanhf(s);
                g_h[idx] = v;
                if (storeOut) outt[idx] = v;
            }
        }

        grid_barrier(&gen_sh, RNN_BLOCKS);
    }
}

extern "C" void kernel_launch(void* const* d_in, const int* in_sizes, int n_in,
                              void* d_out, int out_size) {
    const float* x    = (const float*)d_in[0];
    const float* h0   = (const float*)d_in[1];
    const int*   len  = (const int*)  d_in[2];
    const float* Wih0 = (const float*)d_in[3];
    const float* bih0 = (const float*)d_in[4];
    const float* Whh0 = (const float*)d_in[5];
    const float* bhh0 = (const float*)d_in[6];
    const float* Wih1 = (const float*)d_in[7];
    const float* bih1 = (const float*)d_in[8];
    const float* Whh1 = (const float*)d_in[9];
    const float* bhh1 = (const float*)d_in[10];
    const float* Wfc  = (const float*)d_in[11];
    const float* bfc  = (const float*)d_in[12];
    float* out = (float*)d_out;

    count_kernel<<<1, TT>>>(len);

    init_h_kernel<<<NH/256, 256>>>(h0, 0);
    gemm64<<<dim3(HH/128, TT*2), 128>>>(x, 0, Wih0, bih0, bhh0, nullptr, 0, II, HH, 1);
    rnn_kernel<<<RNN_BLOCKS, 256>>>(Whh0, 1);
    copy_h_kernel<<<NH/256, 256>>>(out, 0);

    init_h_kernel<<<NH/256, 256>>>(h0, 1);
    gemm64<<<dim3(HH/128, TT*2), 128>>>(nullptr, 1, Wih1, bih1, bhh1, nullptr, 0, HH, HH, 1);
    rnn_kernel<<<RNN_BLOCKS, 256>>>(Whh1, 0);
    copy_h_kernel<<<NH/256, 256>>>(out, 1);

    gemm64<<<dim3(CC/128, NN/64), 128>>>(nullptr, 2, Wfc, bfc, nullptr, out, 1, HH, CC, 0);
}